// round 7
// baseline (speedup 1.0000x reference)
#include <cuda_runtime.h>
#include <cuda_fp16.h>

#define HWSZ 36864   // 192*192
#define WIMG 192

__global__ void zero_out_kernel(float* __restrict__ out, int n4) {
    int i = blockIdx.x * blockDim.x + threadIdx.x;
    if (i < n4) reinterpret_cast<float4*>(out)[i] = make_float4(0.f, 0.f, 0.f, 0.f);
}

__device__ __forceinline__ float ex2f(float a) {
    float r;
    asm("ex2.approx.ftz.f32 %0, %1;" : "=f"(r) : "f"(a));
    return r;
}

// split (a,b) into fp16 hi pair + fp16 residual pair (two-term representation)
__device__ __forceinline__ void split2(float a, float b, unsigned& hi, unsigned& lo) {
    __half2 h = __floats2half2_rn(a, b);
    float ra = a - __low2float(h);
    float rb = b - __high2float(h);
    __half2 l = __floats2half2_rn(ra, rb);
    hi = *reinterpret_cast<unsigned*>(&h);
    lo = *reinterpret_cast<unsigned*>(&l);
}

__device__ __forceinline__ void mma16816(float c[4], const unsigned a[4],
                                         unsigned b0, unsigned b1) {
    asm volatile(
        "mma.sync.aligned.m16n8k16.row.col.f32.f16.f16.f32 "
        "{%0,%1,%2,%3}, {%4,%5,%6,%7}, {%8,%9}, {%0,%1,%2,%3};"
        : "+f"(c[0]), "+f"(c[1]), "+f"(c[2]), "+f"(c[3])
        : "r"(a[0]), "r"(a[1]), "r"(a[2]), "r"(a[3]), "r"(b0), "r"(b1));
}

// One warp per (window, head). Tensor-core attention, fp16 split-compensated.
__global__ __launch_bounds__(32) void wdwa_attn_kernel(
    const float* __restrict__ x,    // (576, 192, 192)
    const float* __restrict__ fc,   // (8, 8, 2) cos/sin
    const float* __restrict__ wgt,  // (192, 192)
    float* __restrict__ out)        // (192, 192, 192)
{
    // half2 tiles. Q/K: [64 rows][pitch 20 h2] (12 data + 4 zero-pad + 4 slack)
    // V: k-pair transposed [24 ch][pitch 36 h2] (32 data)
    __shared__ unsigned Qhi[64 * 20], Qlo[64 * 20];
    __shared__ unsigned Khi[64 * 20], Klo[64 * 20];
    __shared__ unsigned Vhi[24 * 36], Vlo[24 * 36];
    __shared__ float cs[64], sn[64];

    const int wi   = blockIdx.x;     // 0..1023 = ih*64 + iw*4 + g
    const int head = blockIdx.y;     // 0..7
    const int lane = threadIdx.x;    // 0..31

    const int ih = wi >> 6;
    const int rem = wi & 63;
    const int iw = rem >> 2;
    const int g  = rem & 3;
    const int rshift = (g & 1) ? 6 : 0;
    const int cshift = (g & 2) ? 6 : 0;

    cs[lane]      = fc[2 * lane];
    sn[lane]      = fc[2 * lane + 1];
    cs[lane + 32] = fc[2 * (lane + 32)];
    sn[lane + 32] = fc[2 * (lane + 32) + 1];
    __syncwarp();

    const int qb = head * 24;
    const int kb = 192 + head * 24;
    const int vb = 384 + head * 24;

    // 1/sqrt(24) * log2(e) folded into q
    const float QSCALE = 0.2944887f;

    // ------------- load + rotate + stage to smem -------------
    // thread owns pixel pair (2*lane, 2*lane+1)
    float v0[24], v1[24];
#pragma unroll
    for (int pix = 0; pix < 2; pix++) {
        const int p  = 2 * lane + pix;
        const int y  = p >> 3;
        const int xx = p & 7;

        int sr = ih * 12 + y;
        if (rshift) sr = (sr < 186) ? sr + 6 : 376 - sr;
        int sc = iw * 12 + xx;
        if (cshift) sc = (sc < 186) ? sc + 6 : 376 - sc;

        const float* xp = x + sr * WIMG + sc;

        float q[24], k[24];
#pragma unroll
        for (int c = 0; c < 24; c++) q[c] = xp[(qb + c) * HWSZ];
#pragma unroll
        for (int c = 0; c < 24; c++) k[c] = xp[(kb + c) * HWSZ];
        float* vv = pix ? v1 : v0;
#pragma unroll
        for (int c = 0; c < 24; c++) vv[c] = xp[(vb + c) * HWSZ];

        // hs_pe rotation on q and k
#pragma unroll
        for (int t = 0; t < 8; t++) {
            const float cy = cs[y * 8 + t],  sy = sn[y * 8 + t];
            const float cx = cs[xx * 8 + t], sx = sn[xx * 8 + t];
            {
                float a = q[3*t], b = q[3*t+1], c2 = q[3*t+2];
                float a2 = a * cy - b * sy;
                float b2 = a * sy + b * cy;
                q[3*t]   = a2;
                q[3*t+1] = b2 * cx - c2 * sx;
                q[3*t+2] = b2 * sx + c2 * cx;
            }
            {
                float a = k[3*t], b = k[3*t+1], c2 = k[3*t+2];
                float a2 = a * cy - b * sy;
                float b2 = a * sy + b * cy;
                k[3*t]   = a2;
                k[3*t+1] = b2 * cx - c2 * sx;
                k[3*t+2] = b2 * sx + c2 * cx;
            }
        }

        const int row = p;
#pragma unroll
        for (int j = 0; j < 12; j++) {
            unsigned hi, lo;
            split2(q[2*j] * QSCALE, q[2*j+1] * QSCALE, hi, lo);
            Qhi[row * 20 + j] = hi; Qlo[row * 20 + j] = lo;
            split2(k[2*j], k[2*j+1], hi, lo);
            Khi[row * 20 + j] = hi; Klo[row * 20 + j] = lo;
        }
#pragma unroll
        for (int j = 12; j < 16; j++) {   // zero-pad k-dim 24..31
            Qhi[row * 20 + j] = 0; Qlo[row * 20 + j] = 0;
            Khi[row * 20 + j] = 0; Klo[row * 20 + j] = 0;
        }
    }
    // V: pack (V[2l][c], V[2l+1][c]) -> Vt[c][l]
#pragma unroll
    for (int c = 0; c < 24; c++) {
        unsigned hi, lo;
        split2(v0[c], v1[c], hi, lo);
        Vhi[c * 36 + lane] = hi;
        Vlo[c * 36 + lane] = lo;
    }
    __syncwarp();

    const int qr = lane >> 2;   // quad row 0..7
    const int qc = lane & 3;    // quad col 0..3

    // ------------- 4 row-blocks of 16 query rows -------------
#pragma unroll
    for (int rb = 0; rb < 4; rb++) {
        const int ar0 = rb * 16 + qr;

        // Q A-fragments (2 k-chunks)
        unsigned aQh[2][4], aQl[2][4];
#pragma unroll
        for (int kc = 0; kc < 2; kc++) {
            const int h2c = kc * 8 + qc;
            aQh[kc][0] = Qhi[ar0 * 20 + h2c];
            aQh[kc][1] = Qhi[(ar0 + 8) * 20 + h2c];
            aQh[kc][2] = Qhi[ar0 * 20 + h2c + 4];
            aQh[kc][3] = Qhi[(ar0 + 8) * 20 + h2c + 4];
            aQl[kc][0] = Qlo[ar0 * 20 + h2c];
            aQl[kc][1] = Qlo[(ar0 + 8) * 20 + h2c];
            aQl[kc][2] = Qlo[ar0 * 20 + h2c + 4];
            aQl[kc][3] = Qlo[(ar0 + 8) * 20 + h2c + 4];
        }

        // S = Q K^T  (8 n-tiles of 8 keys)
        float s8[8][4];
#pragma unroll
        for (int nt = 0; nt < 8; nt++) { s8[nt][0]=0.f; s8[nt][1]=0.f; s8[nt][2]=0.f; s8[nt][3]=0.f; }
#pragma unroll
        for (int kc = 0; kc < 2; kc++) {
#pragma unroll
            for (int nt = 0; nt < 8; nt++) {
                const int ba = (nt * 8 + qr) * 20 + kc * 8 + qc;
                const unsigned b0h = Khi[ba], b1h = Khi[ba + 4];
                const unsigned b0l = Klo[ba], b1l = Klo[ba + 4];
                mma16816(s8[nt], aQh[kc], b0h, b1h);
                mma16816(s8[nt], aQl[kc], b0h, b1h);
                mma16816(s8[nt], aQh[kc], b0l, b1l);
            }
        }

        // softmax over 64 cols; thread holds 16 cols of rows r0 and r1
        float m0 = -1e30f, m1 = -1e30f;
#pragma unroll
        for (int nt = 0; nt < 8; nt++) {
            m0 = fmaxf(m0, fmaxf(s8[nt][0], s8[nt][1]));
            m1 = fmaxf(m1, fmaxf(s8[nt][2], s8[nt][3]));
        }
        m0 = fmaxf(m0, __shfl_xor_sync(0xffffffff, m0, 1));
        m0 = fmaxf(m0, __shfl_xor_sync(0xffffffff, m0, 2));
        m1 = fmaxf(m1, __shfl_xor_sync(0xffffffff, m1, 1));
        m1 = fmaxf(m1, __shfl_xor_sync(0xffffffff, m1, 2));

        float den0 = 0.f, den1 = 0.f;
#pragma unroll
        for (int nt = 0; nt < 8; nt++) {
            s8[nt][0] = ex2f(s8[nt][0] - m0);
            s8[nt][1] = ex2f(s8[nt][1] - m0);
            s8[nt][2] = ex2f(s8[nt][2] - m1);
            s8[nt][3] = ex2f(s8[nt][3] - m1);
            den0 += s8[nt][0] + s8[nt][1];
            den1 += s8[nt][2] + s8[nt][3];
        }
        den0 += __shfl_xor_sync(0xffffffff, den0, 1);
        den0 += __shfl_xor_sync(0xffffffff, den0, 2);
        den1 += __shfl_xor_sync(0xffffffff, den1, 1);
        den1 += __shfl_xor_sync(0xffffffff, den1, 2);

        // P -> A-fragments (register repack; C layout == A layout for k16)
        unsigned pah[4][4], pal[4][4];
#pragma unroll
        for (int kc2 = 0; kc2 < 4; kc2++) {
            const int t0 = 2 * kc2, t1 = 2 * kc2 + 1;
            split2(s8[t0][0], s8[t0][1], pah[kc2][0], pal[kc2][0]);
            split2(s8[t0][2], s8[t0][3], pah[kc2][1], pal[kc2][1]);
            split2(s8[t1][0], s8[t1][1], pah[kc2][2], pal[kc2][2]);
            split2(s8[t1][2], s8[t1][3], pah[kc2][3], pal[kc2][3]);
        }

        // O = P V  (3 n-tiles of 8 channels, k = 64 in 4 chunks)
        float d3[3][4];
#pragma unroll
        for (int nt = 0; nt < 3; nt++) { d3[nt][0]=0.f; d3[nt][1]=0.f; d3[nt][2]=0.f; d3[nt][3]=0.f; }
#pragma unroll
        for (int kc2 = 0; kc2 < 4; kc2++) {
#pragma unroll
            for (int nt = 0; nt < 3; nt++) {
                const int va = (nt * 8 + qr) * 36 + kc2 * 8 + qc;
                const unsigned b0h = Vhi[va], b1h = Vhi[va + 4];
                const unsigned b0l = Vlo[va], b1l = Vlo[va + 4];
                mma16816(d3[nt], pah[kc2], b0h, b1h);
                mma16816(d3[nt], pal[kc2], b0h, b1h);
                mma16816(d3[nt], pah[kc2], b0l, b1l);
            }
        }

        // epilogue: thread owns rows r0=rb*16+qr (regs 0,1) and r0+8 (regs 2,3),
        // channels nt*8 + qc*2, +1
        const float inv0 = 1.0f / den0;
        const float inv1 = 1.0f / den1;
#pragma unroll
        for (int hh = 0; hh < 2; hh++) {
            const int p  = rb * 16 + qr + 8 * hh;
            const int y  = p >> 3;
            const int xx = p & 7;
            const int gr = ih * 12 + y + rshift;
            const int gc = iw * 12 + xx + cshift;
            if (gr < 192 && gc < 192) {
                const float wv = (hh ? inv1 : inv0) / wgt[gr * WIMG + gc];
                float* op = out + head * 24 * HWSZ + gr * WIMG + gc;
#pragma unroll
                for (int nt = 0; nt < 3; nt++) {
                    const int ch = nt * 8 + qc * 2;
                    atomicAdd(op + ch * HWSZ,       d3[nt][2*hh]     * wv);
                    atomicAdd(op + (ch + 1) * HWSZ, d3[nt][2*hh + 1] * wv);
                }
            }
        }
    }
}

extern "C" void kernel_launch(void* const* d_in, const int* in_sizes, int n_in,
                              void* d_out, int out_size) {
    const float* x   = (const float*)d_in[0];
    const float* fc  = (const float*)d_in[1];
    const float* wgt = (const float*)d_in[2];
    float* out = (float*)d_out;

    const int n4 = (192 * 36864) / 4;
    zero_out_kernel<<<(n4 + 255) / 256, 256>>>(out, n4);

    dim3 grid(1024, 8);
    wdwa_attn_kernel<<<grid, 32>>>(x, fc, wgt, out);
}

// round 11
// speedup vs baseline: 1.4964x; 1.4964x over previous
#include <cuda_runtime.h>
#include <cuda_fp16.h>

#define HWSZ 36864   // 192*192
#define WIMG 192

__global__ void zero_out_kernel(float* __restrict__ out, int n4) {
    int i = blockIdx.x * blockDim.x + threadIdx.x;
    if (i < n4) reinterpret_cast<float4*>(out)[i] = make_float4(0.f, 0.f, 0.f, 0.f);
}

__device__ __forceinline__ float ex2f(float a) {
    float r;
    asm("ex2.approx.ftz.f32 %0, %1;" : "=f"(r) : "f"(a));
    return r;
}

// split (a,b) into fp16 hi pair + fp16 residual pair
__device__ __forceinline__ void split2(float a, float b, unsigned& hi, unsigned& lo) {
    __half2 h = __floats2half2_rn(a, b);
    float ra = a - __low2float(h);
    float rb = b - __high2float(h);
    __half2 l = __floats2half2_rn(ra, rb);
    hi = *reinterpret_cast<unsigned*>(&h);
    lo = *reinterpret_cast<unsigned*>(&l);
}

__device__ __forceinline__ unsigned pack_h2(float a, float b) {
    __half2 h = __floats2half2_rn(a, b);
    return *reinterpret_cast<unsigned*>(&h);
}

__device__ __forceinline__ void mma16808(float c[4], unsigned a0, unsigned a1, unsigned b0) {
    asm volatile(
        "mma.sync.aligned.m16n8k8.row.col.f32.f16.f16.f32 "
        "{%0,%1,%2,%3}, {%4,%5}, {%6}, {%0,%1,%2,%3};"
        : "+f"(c[0]), "+f"(c[1]), "+f"(c[2]), "+f"(c[3])
        : "r"(a0), "r"(a1), "r"(b0));
}

// One warp per (window, head). Tensor-core attention, fp16 split-compensated QK,
// single-term fp16 V. smem ~15.9KB -> 14 CTAs/SM.
__global__ __launch_bounds__(32, 14) void wdwa_attn_kernel(
    const float* __restrict__ x,    // (576, 192, 192)
    const float* __restrict__ fc,   // (8, 8, 2) cos/sin
    const float* __restrict__ wgt,  // (192, 192)
    float* __restrict__ out)        // (192, 192, 192)
{
    // Q/K: [64 rows][12 h2], pitch 12 (conflict-free fragment reads)
    // V:   k-pair transposed [24 ch][36], 32 data (pitch 36 conflict-free)
    __shared__ unsigned Qhi[64 * 12], Qlo[64 * 12];
    __shared__ unsigned Khi[64 * 12], Klo[64 * 12];
    __shared__ unsigned Vh[24 * 36];
    __shared__ float cs[64], sn[64];

    const int wi   = blockIdx.x;     // 0..1023 = ih*64 + iw*4 + g
    const int head = blockIdx.y;     // 0..7
    const int lane = threadIdx.x;    // 0..31

    const int ih = wi >> 6;
    const int rem = wi & 63;
    const int iw = rem >> 2;
    const int g  = rem & 3;
    const int rshift = (g & 1) ? 6 : 0;
    const int cshift = (g & 2) ? 6 : 0;

    cs[lane]      = fc[2 * lane];
    sn[lane]      = fc[2 * lane + 1];
    cs[lane + 32] = fc[2 * (lane + 32)];
    sn[lane + 32] = fc[2 * (lane + 32) + 1];
    __syncwarp();

    const int qb = head * 24;
    const int kb = 192 + head * 24;
    const int vb = 384 + head * 24;

    // 1/sqrt(24) * log2(e) folded into q
    const float QSCALE = 0.2944887f;

    // ---------------- V: thread owns pixel pair (2l, 2l+1) ----------------
    {
        const int p0 = 2 * lane, p1 = 2 * lane + 1;
        int sr0 = ih * 12 + (p0 >> 3);
        if (rshift) sr0 = (sr0 < 186) ? sr0 + 6 : 376 - sr0;
        int sc0 = iw * 12 + (p0 & 7);
        if (cshift) sc0 = (sc0 < 186) ? sc0 + 6 : 376 - sc0;
        int sr1 = ih * 12 + (p1 >> 3);
        if (rshift) sr1 = (sr1 < 186) ? sr1 + 6 : 376 - sr1;
        int sc1 = iw * 12 + (p1 & 7);
        if (cshift) sc1 = (sc1 < 186) ? sc1 + 6 : 376 - sc1;

        const float* xa = x + sr0 * WIMG + sc0 + vb * HWSZ;
        const float* xb = x + sr1 * WIMG + sc1 + vb * HWSZ;
        float v0[24], v1[24];
#pragma unroll
        for (int c = 0; c < 24; c++) v0[c] = xa[c * HWSZ];
#pragma unroll
        for (int c = 0; c < 24; c++) v1[c] = xb[c * HWSZ];
#pragma unroll
        for (int c = 0; c < 24; c++) Vh[c * 36 + lane] = pack_h2(v0[c], v1[c]);
    }

    // ---------------- Q/K: thread owns rows (l, l+32) ----------------
#pragma unroll
    for (int pix = 0; pix < 2; pix++) {
        const int p  = lane + 32 * pix;
        const int y  = p >> 3;
        const int xx = p & 7;

        int sr = ih * 12 + y;
        if (rshift) sr = (sr < 186) ? sr + 6 : 376 - sr;
        int sc = iw * 12 + xx;
        if (cshift) sc = (sc < 186) ? sc + 6 : 376 - sc;

        const float* xp = x + sr * WIMG + sc;

        float q[24], k[24];
#pragma unroll
        for (int c = 0; c < 24; c++) q[c] = xp[(qb + c) * HWSZ];
#pragma unroll
        for (int c = 0; c < 24; c++) k[c] = xp[(kb + c) * HWSZ];

        // hs_pe rotation
#pragma unroll
        for (int t = 0; t < 8; t++) {
            const float cy = cs[y * 8 + t],  sy = sn[y * 8 + t];
            const float cx = cs[xx * 8 + t], sx = sn[xx * 8 + t];
            {
                float a = q[3*t], b = q[3*t+1], c2 = q[3*t+2];
                float a2 = a * cy - b * sy;
                float b2 = a * sy + b * cy;
                q[3*t]   = a2;
                q[3*t+1] = b2 * cx - c2 * sx;
                q[3*t+2] = b2 * sx + c2 * cx;
            }
            {
                float a = k[3*t], b = k[3*t+1], c2 = k[3*t+2];
                float a2 = a * cy - b * sy;
                float b2 = a * sy + b * cy;
                k[3*t]   = a2;
                k[3*t+1] = b2 * cx - c2 * sx;
                k[3*t+2] = b2 * sx + c2 * cx;
            }
        }

#pragma unroll
        for (int j = 0; j < 12; j++) {
            unsigned hi, lo;
            split2(q[2*j] * QSCALE, q[2*j+1] * QSCALE, hi, lo);
            Qhi[p * 12 + j] = hi; Qlo[p * 12 + j] = lo;
            split2(k[2*j], k[2*j+1], hi, lo);
            Khi[p * 12 + j] = hi; Klo[p * 12 + j] = lo;
        }
    }
    __syncwarp();

    const int qr = lane >> 2;   // 0..7
    const int qc = lane & 3;    // 0..3

    // ---------------- 4 row-blocks of 16 query rows ----------------
#pragma unroll
    for (int rb = 0; rb < 4; rb++) {
        const int ar0 = rb * 16 + qr;

        // Q A-fragments: 3 k8 chunks, 2 terms
        unsigned aQh[3][2], aQl[3][2];
#pragma unroll
        for (int c = 0; c < 3; c++) {
            const int h2c = 4 * c + qc;
            aQh[c][0] = Qhi[ar0 * 12 + h2c];
            aQh[c][1] = Qhi[(ar0 + 8) * 12 + h2c];
            aQl[c][0] = Qlo[ar0 * 12 + h2c];
            aQl[c][1] = Qlo[(ar0 + 8) * 12 + h2c];
        }

        // S = Q K^T : 8 n-tiles × 3 k8 chunks × 3 split products
        float s8[8][4];
#pragma unroll
        for (int nt = 0; nt < 8; nt++) { s8[nt][0]=0.f; s8[nt][1]=0.f; s8[nt][2]=0.f; s8[nt][3]=0.f; }
#pragma unroll
        for (int c = 0; c < 3; c++) {
#pragma unroll
            for (int nt = 0; nt < 8; nt++) {
                const int ba = (nt * 8 + qr) * 12 + 4 * c + qc;
                const unsigned bh = Khi[ba];
                const unsigned bl = Klo[ba];
                mma16808(s8[nt], aQh[c][0], aQh[c][1], bh);
                mma16808(s8[nt], aQl[c][0], aQl[c][1], bh);
                mma16808(s8[nt], aQh[c][0], aQh[c][1], bl);
            }
        }

        // softmax over 64 keys (rows r0 = ar0, r1 = ar0+8)
        float m0 = -1e30f, m1 = -1e30f;
#pragma unroll
        for (int nt = 0; nt < 8; nt++) {
            m0 = fmaxf(m0, fmaxf(s8[nt][0], s8[nt][1]));
            m1 = fmaxf(m1, fmaxf(s8[nt][2], s8[nt][3]));
        }
        m0 = fmaxf(m0, __shfl_xor_sync(0xffffffff, m0, 1));
        m0 = fmaxf(m0, __shfl_xor_sync(0xffffffff, m0, 2));
        m1 = fmaxf(m1, __shfl_xor_sync(0xffffffff, m1, 1));
        m1 = fmaxf(m1, __shfl_xor_sync(0xffffffff, m1, 2));

        float den0 = 0.f, den1 = 0.f;
#pragma unroll
        for (int nt = 0; nt < 8; nt++) {
            s8[nt][0] = ex2f(s8[nt][0] - m0);
            s8[nt][1] = ex2f(s8[nt][1] - m0);
            s8[nt][2] = ex2f(s8[nt][2] - m1);
            s8[nt][3] = ex2f(s8[nt][3] - m1);
            den0 += s8[nt][0] + s8[nt][1];
            den1 += s8[nt][2] + s8[nt][3];
        }
        den0 += __shfl_xor_sync(0xffffffff, den0, 1);
        den0 += __shfl_xor_sync(0xffffffff, den0, 2);
        den1 += __shfl_xor_sync(0xffffffff, den1, 1);
        den1 += __shfl_xor_sync(0xffffffff, den1, 2);

        // P -> A-fragments (k8): chunk kc2 uses score tile kc2's C-regs directly
        unsigned pah[8][2], pal[8][2];
#pragma unroll
        for (int kc2 = 0; kc2 < 8; kc2++) {
            split2(s8[kc2][0], s8[kc2][1], pah[kc2][0], pal[kc2][0]);
            split2(s8[kc2][2], s8[kc2][3], pah[kc2][1], pal[kc2][1]);
        }

        // O = P V : 3 n-tiles × 8 k8 chunks × 2 P-terms (V single-term)
        float d3[3][4];
#pragma unroll
        for (int nt = 0; nt < 3; nt++) { d3[nt][0]=0.f; d3[nt][1]=0.f; d3[nt][2]=0.f; d3[nt][3]=0.f; }
#pragma unroll
        for (int kc2 = 0; kc2 < 8; kc2++) {
#pragma unroll
            for (int nt = 0; nt < 3; nt++) {
                const unsigned b = Vh[(nt * 8 + qr) * 36 + 4 * kc2 + qc];
                mma16808(d3[nt], pah[kc2][0], pah[kc2][1], b);
                mma16808(d3[nt], pal[kc2][0], pal[kc2][1], b);
            }
        }

        // epilogue
        const float inv0 = 1.0f / den0;
        const float inv1 = 1.0f / den1;
#pragma unroll
        for (int hh = 0; hh < 2; hh++) {
            const int p  = rb * 16 + qr + 8 * hh;
            const int y  = p >> 3;
            const int xx = p & 7;
            const int gr = ih * 12 + y + rshift;
            const int gc = iw * 12 + xx + cshift;
            if (gr < 192 && gc < 192) {
                const float wv = (hh ? inv1 : inv0) / wgt[gr * WIMG + gc];
                float* op = out + head * 24 * HWSZ + gr * WIMG + gc;
#pragma unroll
                for (int nt = 0; nt < 3; nt++) {
                    const int ch = nt * 8 + qc * 2;
                    atomicAdd(op + ch * HWSZ,       d3[nt][2*hh]     * wv);
                    atomicAdd(op + (ch + 1) * HWSZ, d3[nt][2*hh + 1] * wv);
                }
            }
        }
    }
}

extern "C" void kernel_launch(void* const* d_in, const int* in_sizes, int n_in,
                              void* d_out, int out_size) {
    const float* x   = (const float*)d_in[0];
    const float* fc  = (const float*)d_in[1];
    const float* wgt = (const float*)d_in[2];
    float* out = (float*)d_out;

    const int n4 = (192 * 36864) / 4;
    zero_out_kernel<<<(n4 + 255) / 256, 256>>>(out, n4);

    dim3 grid(1024, 8);
    wdwa_attn_kernel<<<grid, 32>>>(x, fc, wgt, out);
}

// round 14
// speedup vs baseline: 1.6420x; 1.0973x over previous
#include <cuda_runtime.h>
#include <cuda_fp16.h>

#define HWSZ 36864   // 192*192
#define WIMG 192

__global__ void zero_out_kernel(float* __restrict__ out, int n4) {
    int i = blockIdx.x * blockDim.x + threadIdx.x;
    if (i < n4) reinterpret_cast<float4*>(out)[i] = make_float4(0.f, 0.f, 0.f, 0.f);
}

__device__ __forceinline__ float ex2f(float a) {
    float r;
    asm("ex2.approx.ftz.f32 %0, %1;" : "=f"(r) : "f"(a));
    return r;
}

// split (a,b) into fp16 hi pair + fp16 residual pair
__device__ __forceinline__ void split2(float a, float b, unsigned& hi, unsigned& lo) {
    __half2 h = __floats2half2_rn(a, b);
    float ra = a - __low2float(h);
    float rb = b - __high2float(h);
    __half2 l = __floats2half2_rn(ra, rb);
    hi = *reinterpret_cast<unsigned*>(&h);
    lo = *reinterpret_cast<unsigned*>(&l);
}

__device__ __forceinline__ unsigned pack_h2(float a, float b) {
    __half2 h = __floats2half2_rn(a, b);
    return *reinterpret_cast<unsigned*>(&h);
}

__device__ __forceinline__ void mma16808(float c[4], unsigned a0, unsigned a1, unsigned b0) {
    asm volatile(
        "mma.sync.aligned.m16n8k8.row.col.f32.f16.f16.f32 "
        "{%0,%1,%2,%3}, {%4,%5}, {%6}, {%0,%1,%2,%3};"
        : "+f"(c[0]), "+f"(c[1]), "+f"(c[2]), "+f"(c[3])
        : "r"(a0), "r"(a1), "r"(b0));
}

// One 128-thread CTA per (window, head): 4 warps, each owning one 16-row block.
__global__ __launch_bounds__(128, 5) void wdwa_attn_kernel(
    const float* __restrict__ x,    // (576, 192, 192)
    const float* __restrict__ fc,   // (8, 8, 2) cos/sin
    const float* __restrict__ wgt,  // (192, 192)
    float* __restrict__ out)        // (192, 192, 192)
{
    __shared__ unsigned Qhi[64 * 12], Qlo[64 * 12];
    __shared__ unsigned Khi[64 * 12], Klo[64 * 12];
    __shared__ unsigned Vh[24 * 36];
    __shared__ float cs[64], sn[64];

    const int wi   = blockIdx.x;     // 0..1023 = ih*64 + iw*4 + g
    const int head = blockIdx.y;     // 0..7
    const int tid  = threadIdx.x;    // 0..127
    const int warp = tid >> 5;
    const int lane = tid & 31;

    const int ih = wi >> 6;
    const int rem = wi & 63;
    const int iw = rem >> 2;
    const int g  = rem & 3;
    const int rshift = (g & 1) ? 6 : 0;
    const int cshift = (g & 2) ? 6 : 0;

    if (tid < 64) { cs[tid] = fc[2 * tid]; sn[tid] = fc[2 * tid + 1]; }

    const int qb = head * 24;
    const int kb = 192 + head * 24;
    const int vb = 384 + head * 24;

    // reflect-mapped source offset of window pixel p
    auto srcOff = [&](int p) -> int {
        const int y = p >> 3, xx = p & 7;
        int sr = ih * 12 + y;
        if (rshift) sr = (sr < 186) ? sr + 6 : 376 - sr;
        int sc = iw * 12 + xx;
        if (cshift) sc = (sc < 186) ? sc + 6 : 376 - sc;
        return sr * WIMG + sc;
    };

    // ---- issue all global loads up front ----
    // V: thread loads pixel (tid&63), channels (tid>>6)*12 .. +12
    const int vpix = tid & 63;
    const int vch0 = (tid >> 6) * 12;
    const float* vp = x + srcOff(vpix) + (vb + vch0) * HWSZ;
    float v[12];
#pragma unroll
    for (int c = 0; c < 12; c++) v[c] = vp[c * HWSZ];

    // Q (tid<64) or K (tid>=64), row = tid&63
    const int row = tid & 63;
    const bool isQ = (tid < 64);
    const float* rp = x + srcOff(row) + (isQ ? qb : kb) * HWSZ;
    float rqk[24];
#pragma unroll
    for (int c = 0; c < 24; c++) rqk[c] = rp[c * HWSZ];

    __syncthreads();  // cs/sn ready

    // hs_pe rotation on this row
    {
        const int ry = row >> 3, rx = row & 7;
#pragma unroll
        for (int t = 0; t < 8; t++) {
            const float cy = cs[ry * 8 + t], sy = sn[ry * 8 + t];
            const float cx = cs[rx * 8 + t], sx = sn[rx * 8 + t];
            float a = rqk[3*t], b = rqk[3*t+1], c2 = rqk[3*t+2];
            float a2 = a * cy - b * sy;
            float b2 = a * sy + b * cy;
            rqk[3*t]   = a2;
            rqk[3*t+1] = b2 * cx - c2 * sx;
            rqk[3*t+2] = b2 * sx + c2 * cx;
        }
    }

    // 1/sqrt(24) * log2(e) folded into q
    const float QSCALE = 0.2944887f;
    const float rsc = isQ ? QSCALE : 1.0f;
    unsigned* Hi = isQ ? Qhi : Khi;
    unsigned* Lo = isQ ? Qlo : Klo;
#pragma unroll
    for (int j = 0; j < 12; j++) {
        unsigned hi, lo;
        split2(rqk[2*j] * rsc, rqk[2*j+1] * rsc, hi, lo);
        Hi[row * 12 + j] = hi;
        Lo[row * 12 + j] = lo;
    }

    // V pack: even-pixel thread packs (v_even, v_odd) via shuffle with tid^1
#pragma unroll
    for (int c = 0; c < 12; c++) {
        const float other = __shfl_xor_sync(0xffffffff, v[c], 1);
        if (!(vpix & 1)) Vh[(vch0 + c) * 36 + (vpix >> 1)] = pack_h2(v[c], other);
    }
    __syncthreads();

    // ---------------- mainloop: warp owns row-block rb = warp ----------------
    const int qr = lane >> 2;   // 0..7
    const int qc = lane & 3;    // 0..3
    const int ar0 = warp * 16 + qr;

    // Q A-fragments: 3 k8 chunks, 2 terms
    unsigned aQh[3][2], aQl[3][2];
#pragma unroll
    for (int c = 0; c < 3; c++) {
        const int h2c = 4 * c + qc;
        aQh[c][0] = Qhi[ar0 * 12 + h2c];
        aQh[c][1] = Qhi[(ar0 + 8) * 12 + h2c];
        aQl[c][0] = Qlo[ar0 * 12 + h2c];
        aQl[c][1] = Qlo[(ar0 + 8) * 12 + h2c];
    }

    // S = Q K^T : 8 n-tiles × 3 k8 chunks × 3 split products
    float s8[8][4];
#pragma unroll
    for (int nt = 0; nt < 8; nt++) { s8[nt][0]=0.f; s8[nt][1]=0.f; s8[nt][2]=0.f; s8[nt][3]=0.f; }
#pragma unroll
    for (int c = 0; c < 3; c++) {
#pragma unroll
        for (int nt = 0; nt < 8; nt++) {
            const int ba = (nt * 8 + qr) * 12 + 4 * c + qc;
            const unsigned bh = Khi[ba];
            const unsigned bl = Klo[ba];
            mma16808(s8[nt], aQh[c][0], aQh[c][1], bh);
            mma16808(s8[nt], aQl[c][0], aQl[c][1], bh);
            mma16808(s8[nt], aQh[c][0], aQh[c][1], bl);
        }
    }

    // softmax over 64 keys (rows r0 = ar0, r1 = ar0 + 8)
    float m0 = -1e30f, m1 = -1e30f;
#pragma unroll
    for (int nt = 0; nt < 8; nt++) {
        m0 = fmaxf(m0, fmaxf(s8[nt][0], s8[nt][1]));
        m1 = fmaxf(m1, fmaxf(s8[nt][2], s8[nt][3]));
    }
    m0 = fmaxf(m0, __shfl_xor_sync(0xffffffff, m0, 1));
    m0 = fmaxf(m0, __shfl_xor_sync(0xffffffff, m0, 2));
    m1 = fmaxf(m1, __shfl_xor_sync(0xffffffff, m1, 1));
    m1 = fmaxf(m1, __shfl_xor_sync(0xffffffff, m1, 2));

    float den0 = 0.f, den1 = 0.f;
#pragma unroll
    for (int nt = 0; nt < 8; nt++) {
        s8[nt][0] = ex2f(s8[nt][0] - m0);
        s8[nt][1] = ex2f(s8[nt][1] - m0);
        s8[nt][2] = ex2f(s8[nt][2] - m1);
        s8[nt][3] = ex2f(s8[nt][3] - m1);
        den0 += s8[nt][0] + s8[nt][1];
        den1 += s8[nt][2] + s8[nt][3];
    }
    den0 += __shfl_xor_sync(0xffffffff, den0, 1);
    den0 += __shfl_xor_sync(0xffffffff, den0, 2);
    den1 += __shfl_xor_sync(0xffffffff, den1, 1);
    den1 += __shfl_xor_sync(0xffffffff, den1, 2);

    // O = P V : 3 n-tiles × 8 k8 chunks × 2 P-terms (V single-term).
    // P fragments built on the fly from s8 (C layout == A layout).
    float d3[3][4];
#pragma unroll
    for (int nt = 0; nt < 3; nt++) { d3[nt][0]=0.f; d3[nt][1]=0.f; d3[nt][2]=0.f; d3[nt][3]=0.f; }
#pragma unroll
    for (int kc2 = 0; kc2 < 8; kc2++) {
        unsigned p0h, p0l, p1h, p1l;
        split2(s8[kc2][0], s8[kc2][1], p0h, p0l);
        split2(s8[kc2][2], s8[kc2][3], p1h, p1l);
#pragma unroll
        for (int nt = 0; nt < 3; nt++) {
            const unsigned b = Vh[(nt * 8 + qr) * 36 + 4 * kc2 + qc];
            mma16808(d3[nt], p0h, p1h, b);
            mma16808(d3[nt], p0l, p1l, b);
        }
    }

    // epilogue
    const float inv0 = 1.0f / den0;
    const float inv1 = 1.0f / den1;
#pragma unroll
    for (int hh = 0; hh < 2; hh++) {
        const int p  = warp * 16 + qr + 8 * hh;
        const int y  = p >> 3;
        const int xx = p & 7;
        const int gr = ih * 12 + y + rshift;
        const int gc = iw * 12 + xx + cshift;
        if (gr < 192 && gc < 192) {
            const float wv = (hh ? inv1 : inv0) / wgt[gr * WIMG + gc];
            float* op = out + head * 24 * HWSZ + gr * WIMG + gc;
#pragma unroll
            for (int nt = 0; nt < 3; nt++) {
                const int ch = nt * 8 + qc * 2;
                atomicAdd(op + ch * HWSZ,       d3[nt][2*hh]     * wv);
                atomicAdd(op + (ch + 1) * HWSZ, d3[nt][2*hh + 1] * wv);
            }
        }
    }
}

extern "C" void kernel_launch(void* const* d_in, const int* in_sizes, int n_in,
                              void* d_out, int out_size) {
    const float* x   = (const float*)d_in[0];
    const float* fc  = (const float*)d_in[1];
    const float* wgt = (const float*)d_in[2];
    float* out = (float*)d_out;

    const int n4 = (192 * 36864) / 4;
    zero_out_kernel<<<(n4 + 255) / 256, 256>>>(out, n4);

    dim3 grid(1024, 8);
    wdwa_attn_kernel<<<grid, 128>>>(x, fc, wgt, out);
}

// round 15
// speedup vs baseline: 2.3342x; 1.4215x over previous
#include <cuda_runtime.h>
#include <cuda_fp16.h>

#define HWSZ 36864   // 192*192
#define WIMG 192

__global__ void zero_out_kernel(float* __restrict__ out, int n4) {
    int i = blockIdx.x * blockDim.x + threadIdx.x;
    if (i < n4) reinterpret_cast<float4*>(out)[i] = make_float4(0.f, 0.f, 0.f, 0.f);
}

__device__ __forceinline__ float ex2f(float a) {
    float r;
    asm("ex2.approx.ftz.f32 %0, %1;" : "=f"(r) : "f"(a));
    return r;
}

__device__ __forceinline__ void split2(float a, float b, unsigned& hi, unsigned& lo) {
    __half2 h = __floats2half2_rn(a, b);
    float ra = a - __low2float(h);
    float rb = b - __high2float(h);
    __half2 l = __floats2half2_rn(ra, rb);
    hi = *reinterpret_cast<unsigned*>(&h);
    lo = *reinterpret_cast<unsigned*>(&l);
}

__device__ __forceinline__ unsigned pack_h2(float a, float b) {
    __half2 h = __floats2half2_rn(a, b);
    return *reinterpret_cast<unsigned*>(&h);
}

__device__ __forceinline__ void mma16808(float c[4], unsigned a0, unsigned a1, unsigned b0) {
    asm volatile(
        "mma.sync.aligned.m16n8k8.row.col.f32.f16.f16.f32 "
        "{%0,%1,%2,%3}, {%4,%5}, {%6}, {%0,%1,%2,%3};"
        : "+f"(c[0]), "+f"(c[1]), "+f"(c[2]), "+f"(c[3])
        : "r"(a0), "r"(a1), "r"(b0));
}

__device__ __forceinline__ void red2(float* p, float a, float b) {
    asm volatile("red.global.add.v2.f32 [%0], {%1, %2};"
                 :: "l"(p), "f"(a), "f"(b) : "memory");
}

// shared memory word offsets (unsigned/float words)
#define OFF_QHI 0            // 64*12 = 768
#define OFF_QLO 768          // 768
#define OFF_KHI 1536         // 768
#define OFF_KLO 2304         // 768
#define OFF_VH  3072         // 24*36 = 864
#define OFF_CS  3936         // 64
#define OFF_SN  4000         // 64
#define OFF_SCL 4064         // 64
#define SMEM_WORDS 4128
// O overlay: [24 ch][pitch 66] floats at offset 0 (over Q/K tiles, used post-sync)
#define OPITCH 66

// One 128-thread CTA per (window, head): 4 warps, each owning one 16-row block.
__global__ __launch_bounds__(128, 6) void wdwa_attn_kernel(
    const float* __restrict__ x,    // (576, 192, 192)
    const float* __restrict__ fc,   // (8, 8, 2) cos/sin
    const float* __restrict__ wgt,  // (192, 192)
    float* __restrict__ out)        // (192, 192, 192)
{
    __shared__ unsigned SM[SMEM_WORDS];
    unsigned* Qhi = SM + OFF_QHI;
    unsigned* Qlo = SM + OFF_QLO;
    unsigned* Khi = SM + OFF_KHI;
    unsigned* Klo = SM + OFF_KLO;
    unsigned* Vh  = SM + OFF_VH;
    float* cs  = reinterpret_cast<float*>(SM + OFF_CS);
    float* sn  = reinterpret_cast<float*>(SM + OFF_SN);
    float* scl = reinterpret_cast<float*>(SM + OFF_SCL);
    float* Osm = reinterpret_cast<float*>(SM);   // overlay

    const int wi   = blockIdx.x;     // 0..1023 = ih*64 + iw*4 + g
    const int head = blockIdx.y;     // 0..7
    const int tid  = threadIdx.x;    // 0..127
    const int warp = tid >> 5;
    const int lane = tid & 31;

    const int ih = wi >> 6;
    const int rem = wi & 63;
    const int iw = rem >> 2;
    const int g  = rem & 3;
    const int rshift = (g & 1) ? 6 : 0;
    const int cshift = (g & 2) ? 6 : 0;

    if (tid < 64) { cs[tid] = fc[2 * tid]; sn[tid] = fc[2 * tid + 1]; }

    const int qb = head * 24;
    const int kb = 192 + head * 24;
    const int vb = 384 + head * 24;

    auto srcOff = [&](int p) -> int {
        const int y = p >> 3, xx = p & 7;
        int sr = ih * 12 + y;
        if (rshift) sr = (sr < 186) ? sr + 6 : 376 - sr;
        int sc = iw * 12 + xx;
        if (cshift) sc = (sc < 186) ? sc + 6 : 376 - sc;
        return sr * WIMG + sc;
    };

    // ---- global loads ----
    const int vpix = tid & 63;
    const int vch0 = (tid >> 6) * 12;
    const float* vp = x + srcOff(vpix) + (vb + vch0) * HWSZ;
    float v[12];
#pragma unroll
    for (int c = 0; c < 12; c++) v[c] = vp[c * HWSZ];

    const int row = tid & 63;
    const bool isQ = (tid < 64);
    const float* rp = x + srcOff(row) + (isQ ? qb : kb) * HWSZ;
    float rqk[24];
#pragma unroll
    for (int c = 0; c < 24; c++) rqk[c] = rp[c * HWSZ];

    __syncthreads();  // cs/sn ready

    // hs_pe rotation
    {
        const int ry = row >> 3, rx = row & 7;
#pragma unroll
        for (int t = 0; t < 8; t++) {
            const float cy = cs[ry * 8 + t], sy = sn[ry * 8 + t];
            const float cx = cs[rx * 8 + t], sx = sn[rx * 8 + t];
            float a = rqk[3*t], b = rqk[3*t+1], c2 = rqk[3*t+2];
            float a2 = a * cy - b * sy;
            float b2 = a * sy + b * cy;
            rqk[3*t]   = a2;
            rqk[3*t+1] = b2 * cx - c2 * sx;
            rqk[3*t+2] = b2 * sx + c2 * cx;
        }
    }

    const float QSCALE = 0.2944887f;   // 1/sqrt(24) * log2(e)
    const float rsc = isQ ? QSCALE : 1.0f;
    unsigned* Hi = isQ ? Qhi : Khi;
    unsigned* Lo = isQ ? Qlo : Klo;
#pragma unroll
    for (int j = 0; j < 12; j++) {
        unsigned hi, lo;
        split2(rqk[2*j] * rsc, rqk[2*j+1] * rsc, hi, lo);
        Hi[row * 12 + j] = hi;
        Lo[row * 12 + j] = lo;
    }

#pragma unroll
    for (int c = 0; c < 12; c++) {
        const float other = __shfl_xor_sync(0xffffffff, v[c], 1);
        if (!(vpix & 1)) Vh[(vch0 + c) * 36 + (vpix >> 1)] = pack_h2(v[c], other);
    }
    __syncthreads();

    // ---------------- mainloop: warp owns row-block warp ----------------
    const int qr = lane >> 2;
    const int qc = lane & 3;
    const int ar0 = warp * 16 + qr;

    unsigned aQh[3][2], aQl[3][2];
#pragma unroll
    for (int c = 0; c < 3; c++) {
        const int h2c = 4 * c + qc;
        aQh[c][0] = Qhi[ar0 * 12 + h2c];
        aQh[c][1] = Qhi[(ar0 + 8) * 12 + h2c];
        aQl[c][0] = Qlo[ar0 * 12 + h2c];
        aQl[c][1] = Qlo[(ar0 + 8) * 12 + h2c];
    }

    float s8[8][4];
#pragma unroll
    for (int nt = 0; nt < 8; nt++) { s8[nt][0]=0.f; s8[nt][1]=0.f; s8[nt][2]=0.f; s8[nt][3]=0.f; }
#pragma unroll
    for (int c = 0; c < 3; c++) {
#pragma unroll
        for (int nt = 0; nt < 8; nt++) {
            const int ba = (nt * 8 + qr) * 12 + 4 * c + qc;
            const unsigned bh = Khi[ba];
            const unsigned bl = Klo[ba];
            mma16808(s8[nt], aQh[c][0], aQh[c][1], bh);
            mma16808(s8[nt], aQl[c][0], aQl[c][1], bh);
            mma16808(s8[nt], aQh[c][0], aQh[c][1], bl);
        }
    }

    float m0 = -1e30f, m1 = -1e30f;
#pragma unroll
    for (int nt = 0; nt < 8; nt++) {
        m0 = fmaxf(m0, fmaxf(s8[nt][0], s8[nt][1]));
        m1 = fmaxf(m1, fmaxf(s8[nt][2], s8[nt][3]));
    }
    m0 = fmaxf(m0, __shfl_xor_sync(0xffffffff, m0, 1));
    m0 = fmaxf(m0, __shfl_xor_sync(0xffffffff, m0, 2));
    m1 = fmaxf(m1, __shfl_xor_sync(0xffffffff, m1, 1));
    m1 = fmaxf(m1, __shfl_xor_sync(0xffffffff, m1, 2));

    float den0 = 0.f, den1 = 0.f;
#pragma unroll
    for (int nt = 0; nt < 8; nt++) {
        s8[nt][0] = ex2f(s8[nt][0] - m0);
        s8[nt][1] = ex2f(s8[nt][1] - m0);
        s8[nt][2] = ex2f(s8[nt][2] - m1);
        s8[nt][3] = ex2f(s8[nt][3] - m1);
        den0 += s8[nt][0] + s8[nt][1];
        den1 += s8[nt][2] + s8[nt][3];
    }
    den0 += __shfl_xor_sync(0xffffffff, den0, 1);
    den0 += __shfl_xor_sync(0xffffffff, den0, 2);
    den1 += __shfl_xor_sync(0xffffffff, den1, 1);
    den1 += __shfl_xor_sync(0xffffffff, den1, 2);

    float d3[3][4];
#pragma unroll
    for (int nt = 0; nt < 3; nt++) { d3[nt][0]=0.f; d3[nt][1]=0.f; d3[nt][2]=0.f; d3[nt][3]=0.f; }
#pragma unroll
    for (int kc2 = 0; kc2 < 8; kc2++) {
        unsigned p0h, p0l, p1h, p1l;
        split2(s8[kc2][0], s8[kc2][1], p0h, p0l);
        split2(s8[kc2][2], s8[kc2][3], p1h, p1l);
#pragma unroll
        for (int nt = 0; nt < 3; nt++) {
            const unsigned b = Vh[(nt * 8 + qr) * 36 + 4 * kc2 + qc];
            mma16808(d3[nt], p0h, p1h, b);
            mma16808(d3[nt], p0l, p1l, b);
        }
    }

    // ---------------- epilogue: stage O + per-pixel scale in smem ----------------
    __syncthreads();   // everyone done reading Q/K tiles (O overlays them)

    // per-pixel scale: lanes with qc==0 own pixels p0 = warp*16+qr and p0+8
    if (qc == 0) {
        const float inv0 = 1.0f / den0;
        const float inv1 = 1.0f / den1;
#pragma unroll
        for (int hh = 0; hh < 2; hh++) {
            const int p  = warp * 16 + qr + 8 * hh;
            const int gr = ih * 12 + (p >> 3) + rshift;
            const int gc = iw * 12 + (p & 7) + cshift;
            const bool valid = (gr < 192) && (gc < 192);
            const float w = valid ? wgt[gr * WIMG + gc] : 1.0f;
            scl[p] = (hh ? inv1 : inv0) / w;
        }
    }

    // O[ch][p], pitch 66
#pragma unroll
    for (int hh = 0; hh < 2; hh++) {
        const int p = warp * 16 + qr + 8 * hh;
#pragma unroll
        for (int nt = 0; nt < 3; nt++) {
            const int ch = nt * 8 + 2 * qc;
            Osm[ch * OPITCH + p]       = d3[nt][2*hh];
            Osm[(ch + 1) * OPITCH + p] = d3[nt][2*hh + 1];
        }
    }
    __syncthreads();

    // coalesced reduction: warp owns 6 channels, lane owns pixel pair (2l, 2l+1)
    {
        const int pp = lane;
        const int gr = ih * 12 + (pp >> 2) + rshift;
        const int gc = iw * 12 + ((pp & 3) << 1) + cshift;
        const bool valid = (gr < 192) && (gc < 192);
        const float s0 = scl[2 * pp];
        const float s1 = scl[2 * pp + 1];
        float* obase = out + (head * 24) * HWSZ + gr * WIMG + gc;
#pragma unroll
        for (int k = 0; k < 6; k++) {
            const int c = 6 * warp + k;
            const float2 o = *reinterpret_cast<const float2*>(Osm + c * OPITCH + 2 * pp);
            if (valid) red2(obase + c * HWSZ, o.x * s0, o.y * s1);
        }
    }
}

extern "C" void kernel_launch(void* const* d_in, const int* in_sizes, int n_in,
                              void* d_out, int out_size) {
    const float* x   = (const float*)d_in[0];
    const float* fc  = (const float*)d_in[1];
    const float* wgt = (const float*)d_in[2];
    float* out = (float*)d_out;

    const int n4 = (192 * 36864) / 4;
    zero_out_kernel<<<(n4 + 255) / 256, 256>>>(out, n4);

    dim3 grid(1024, 8);
    wdwa_attn_kernel<<<grid, 128>>>(x, fc, wgt, out);
}